// round 1
// baseline (speedup 1.0000x reference)
#include <cuda_runtime.h>

// Problem constants (fixed for this dataset)
#define BB   4
#define CC   128
#define HH   128
#define WW   128
#define GG   4
#define GCH  32      // channels per group
#define PP   9       // K*K taps
#define NOFF 72      // G*P*2
#define NMSK 36      // G*P
#define TILE 16      // pixels per block
#define NTHR 256

__global__ __launch_bounds__(NTHR) void dcnv3_fused(
    const float* __restrict__ in,     // (B,H,W,C) channel-last (view of (B,C,H,W))
    const float* __restrict__ Woff,   // (C, 72) row-major
    const float* __restrict__ boff,   // (72)
    const float* __restrict__ Wmask,  // (C, 36) row-major
    const float* __restrict__ bmask,  // (36)
    float* __restrict__ out)          // (B,H,W,C) channel-last
{
    __shared__ float xs[TILE][CC];            // 8 KB: input features for the 16 pixels
    __shared__ float offs[TILE][NOFF];        // 4.5 KB
    __shared__ float msk[TILE][NMSK];         // 2.25 KB (logits -> softmax in place)
    __shared__ int   sidx[TILE][NMSK][4];     // 9 KB: 4 corner element-offsets (ch 0)
    __shared__ float swt[TILE][NMSK][4];      // 9 KB: 4 corner weights * mask (0 if invalid)

    const int tid = threadIdx.x;
    const int blk = blockIdx.x;
    const int wt = blk % (WW / TILE);
    const int h  = (blk / (WW / TILE)) % HH;
    const int b  = blk / ((WW / TILE) * HH);
    const int w0 = wt * TILE;

    // ---- load the 16 pixels' features (contiguous 16*128 floats) ----
    const float4* xbase4 = reinterpret_cast<const float4*>(
        in + (((size_t)b * HH + h) * WW + w0) * CC);
    float4* xs4 = reinterpret_cast<float4*>(&xs[0][0]);
    #pragma unroll
    for (int i = tid; i < TILE * CC / 4; i += NTHR) xs4[i] = xbase4[i];
    __syncthreads();

    // ---- phase 1: offset (72) + mask-logit (36) matvecs per pixel ----
    for (int idx = tid; idx < TILE * (NOFF + NMSK); idx += NTHR) {
        const int pp = idx / (NOFF + NMSK);
        const int j  = idx % (NOFF + NMSK);
        const float* xp = xs[pp];
        if (j < NOFF) {
            float acc = boff[j];
            const float* Wc = Woff + j;
            #pragma unroll 8
            for (int k = 0; k < CC; k++) acc = fmaf(xp[k], Wc[k * NOFF], acc);
            offs[pp][j] = acc;
        } else {
            const int jm = j - NOFF;
            float acc = bmask[jm];
            const float* Wc = Wmask + jm;
            #pragma unroll 8
            for (int k = 0; k < CC; k++) acc = fmaf(xp[k], Wc[k * NMSK], acc);
            msk[pp][jm] = acc;
        }
    }
    __syncthreads();

    // ---- phase 2: softmax over the 9 taps per (pixel, group) ----
    if (tid < TILE * GG) {
        const int pp = tid / GG, g = tid % GG;
        float* m = &msk[pp][g * PP];
        float mx = m[0];
        #pragma unroll
        for (int p = 1; p < PP; p++) mx = fmaxf(mx, m[p]);
        float e[PP], s = 0.f;
        #pragma unroll
        for (int p = 0; p < PP; p++) { e[p] = __expf(m[p] - mx); s += e[p]; }
        const float inv = 1.f / s;
        #pragma unroll
        for (int p = 0; p < PP; p++) m[p] = e[p] * inv;
    }
    __syncthreads();

    // ---- phase 2.5: per-(pixel,g,p) corner indices + mask-folded weights ----
    for (int idx = tid; idx < TILE * NMSK; idx += NTHR) {
        const int pp = idx / NMSK;
        const int gp = idx % NMSK;
        const int p  = gp % PP;
        const float dx = offs[pp][gp * 2 + 0];
        const float dy = offs[pp][gp * 2 + 1];
        // padded coords: px = w + p/3 + dx ; py = h + p%3 + dy
        const float px = (float)(w0 + pp) + (float)(p / 3) + dx;
        const float py = (float)h + (float)(p % 3) + dy;
        const float x0f = floorf(px), y0f = floorf(py);
        const float tx = px - x0f, ty = py - y0f;
        const int ix0 = (int)x0f, iy0 = (int)y0f;
        const float m = msk[pp][gp];

        const float wgt[4] = { (1.f - tx) * (1.f - ty) * m,
                               tx * (1.f - ty) * m,
                               (1.f - tx) * ty * m,
                               tx * ty * m };
        const int cx[4] = { ix0, ix0 + 1, ix0,     ix0 + 1 };
        const int cy[4] = { iy0, iy0,     iy0 + 1, iy0 + 1 };
        #pragma unroll
        for (int k = 0; k < 4; k++) {
            // nonzero contribution only if padded coord in [1,128] both axes
            const bool ok = ((unsigned)(cx[k] - 1) < (unsigned)WW) &&
                            ((unsigned)(cy[k] - 1) < (unsigned)HH);
            swt[pp][gp][k]  = ok ? wgt[k] : 0.f;
            sidx[pp][gp][k] = ok ? (((b * HH + (cy[k] - 1)) * WW + (cx[k] - 1)) * CC) : 0;
        }
    }
    __syncthreads();

    // ---- phase 3: gather + accumulate. warp = pixel, lane = float4 channel slot ----
    const int c4 = tid & 31;          // float4 slot -> channels [4*c4, 4*c4+3]
    const int g  = c4 >> 3;           // group of this channel slot
    const float4* in4 = reinterpret_cast<const float4*>(in);
    float4* out4 = reinterpret_cast<float4*>(out);

    #pragma unroll
    for (int pass = 0; pass < 2; pass++) {
        const int pp = (tid >> 5) + pass * 8;
        float4 acc = make_float4(0.f, 0.f, 0.f, 0.f);
        #pragma unroll
        for (int p = 0; p < PP; p++) {
            const int gp = g * PP + p;
            const int4   id = *reinterpret_cast<const int4*>(sidx[pp][gp]);
            const float4 wv = *reinterpret_cast<const float4*>(swt[pp][gp]);
            if (wv.x != 0.f) {
                const float4 v = in4[(id.x >> 2) + c4];
                acc.x = fmaf(wv.x, v.x, acc.x); acc.y = fmaf(wv.x, v.y, acc.y);
                acc.z = fmaf(wv.x, v.z, acc.z); acc.w = fmaf(wv.x, v.w, acc.w);
            }
            if (wv.y != 0.f) {
                const float4 v = in4[(id.y >> 2) + c4];
                acc.x = fmaf(wv.y, v.x, acc.x); acc.y = fmaf(wv.y, v.y, acc.y);
                acc.z = fmaf(wv.y, v.z, acc.z); acc.w = fmaf(wv.y, v.w, acc.w);
            }
            if (wv.z != 0.f) {
                const float4 v = in4[(id.z >> 2) + c4];
                acc.x = fmaf(wv.z, v.x, acc.x); acc.y = fmaf(wv.z, v.y, acc.y);
                acc.z = fmaf(wv.z, v.z, acc.z); acc.w = fmaf(wv.z, v.w, acc.w);
            }
            if (wv.w != 0.f) {
                const float4 v = in4[(id.w >> 2) + c4];
                acc.x = fmaf(wv.w, v.x, acc.x); acc.y = fmaf(wv.w, v.y, acc.y);
                acc.z = fmaf(wv.w, v.z, acc.z); acc.w = fmaf(wv.w, v.w, acc.w);
            }
        }
        const size_t o = (((size_t)b * HH + h) * WW + (w0 + pp)) * (CC / 4) + c4;
        out4[o] = acc;
    }
}

extern "C" void kernel_launch(void* const* d_in, const int* in_sizes, int n_in,
                              void* d_out, int out_size) {
    const float* inp   = (const float*)d_in[0];
    const float* Woff  = (const float*)d_in[1];
    const float* boff  = (const float*)d_in[2];
    const float* Wmask = (const float*)d_in[3];
    const float* bmask = (const float*)d_in[4];
    float* out = (float*)d_out;

    const int nblocks = BB * HH * (WW / TILE);   // 4*128*8 = 4096
    dcnv3_fused<<<nblocks, NTHR>>>(inp, Woff, boff, Wmask, bmask, out);
}

// round 2
// speedup vs baseline: 1.7182x; 1.7182x over previous
#include <cuda_runtime.h>

// Problem constants (fixed for this dataset)
#define BB   4
#define CC   128
#define HH   128
#define WW   128
#define GG   4
#define GCH  32      // channels per group
#define PP   9       // K*K taps
#define NOFF 72      // G*P*2
#define NMSK 36      // G*P
#define TILE 16      // pixels per block
#define NTHR 256

__global__ __launch_bounds__(NTHR) void dcnv3_fused(
    const float* __restrict__ in,     // (B,H,W,C) channel-last (view of (B,C,H,W))
    const float* __restrict__ Woff,   // (C, 72) row-major
    const float* __restrict__ boff,   // (72)
    const float* __restrict__ Wmask,  // (C, 36) row-major
    const float* __restrict__ bmask,  // (36)
    float* __restrict__ out)          // (B,H,W,C) channel-last
{
    __shared__ float xs[TILE][CC];            // 8 KB: input features for the 16 pixels
    __shared__ float offs[TILE][NOFF];        // 4.5 KB
    __shared__ float msk[TILE][NMSK];         // 2.25 KB (logits -> softmax in place)
    __shared__ int   sidx[TILE][NMSK][4];     // 9 KB: 4 corner element-offsets (ch 0)
    __shared__ float swt[TILE][NMSK][4];      // 9 KB: 4 corner weights * mask (0 if invalid)

    const int tid = threadIdx.x;
    const int blk = blockIdx.x;
    const int wt = blk % (WW / TILE);
    const int h  = (blk / (WW / TILE)) % HH;
    const int b  = blk / ((WW / TILE) * HH);
    const int w0 = wt * TILE;

    // ---- load the 16 pixels' features (contiguous 16*128 floats) ----
    const float4* xbase4 = reinterpret_cast<const float4*>(
        in + (((size_t)b * HH + h) * WW + w0) * CC);
    float4* xs4 = reinterpret_cast<float4*>(&xs[0][0]);
    #pragma unroll
    for (int i = tid; i < TILE * CC / 4; i += NTHR) xs4[i] = xbase4[i];
    __syncthreads();

    // ---- phase 1: register-tiled matvec.  2 pixels x 4 outputs per thread.
    // 27 j-quads (18 offset quads + 9 mask quads) x 8 pixel-pairs = 216 threads.
    if (tid < 216) {
        const int pair = tid / 27;           // pixel pair 0..7
        const int jq   = tid % 27;           // j quad
        const int p0 = pair * 2, p1 = p0 + 1;
        const bool is_off = (jq < 18);
        const int j0 = is_off ? jq * 4 : (jq - 18) * 4;
        const float* Wbase = is_off ? (Woff + j0) : (Wmask + j0);
        const int wstride4 = (is_off ? NOFF : NMSK) / 4;   // row stride in float4
        const float4* W4 = reinterpret_cast<const float4*>(Wbase);
        const float* bias = is_off ? boff : bmask;

        float4 acc0 = make_float4(0.f, 0.f, 0.f, 0.f);
        float4 acc1 = make_float4(0.f, 0.f, 0.f, 0.f);
        const float4* xa4 = reinterpret_cast<const float4*>(xs[p0]);
        const float4* xb4 = reinterpret_cast<const float4*>(xs[p1]);

        #pragma unroll 4
        for (int k4 = 0; k4 < CC / 4; k4++) {
            const float4 xa = xa4[k4];
            const float4 xb = xb4[k4];
            const float xav[4] = { xa.x, xa.y, xa.z, xa.w };
            const float xbv[4] = { xb.x, xb.y, xb.z, xb.w };
            #pragma unroll
            for (int kk = 0; kk < 4; kk++) {
                const float4 w = W4[(size_t)(k4 * 4 + kk) * wstride4];
                acc0.x = fmaf(xav[kk], w.x, acc0.x);
                acc0.y = fmaf(xav[kk], w.y, acc0.y);
                acc0.z = fmaf(xav[kk], w.z, acc0.z);
                acc0.w = fmaf(xav[kk], w.w, acc0.w);
                acc1.x = fmaf(xbv[kk], w.x, acc1.x);
                acc1.y = fmaf(xbv[kk], w.y, acc1.y);
                acc1.z = fmaf(xbv[kk], w.z, acc1.z);
                acc1.w = fmaf(xbv[kk], w.w, acc1.w);
            }
        }
        const float4 bv = *reinterpret_cast<const float4*>(bias + j0);
        acc0.x += bv.x; acc0.y += bv.y; acc0.z += bv.z; acc0.w += bv.w;
        acc1.x += bv.x; acc1.y += bv.y; acc1.z += bv.z; acc1.w += bv.w;

        if (is_off) {
            *reinterpret_cast<float4*>(&offs[p0][j0]) = acc0;
            *reinterpret_cast<float4*>(&offs[p1][j0]) = acc1;
        } else {
            *reinterpret_cast<float4*>(&msk[p0][j0]) = acc0;
            *reinterpret_cast<float4*>(&msk[p1][j0]) = acc1;
        }
    }
    __syncthreads();

    // ---- phase 2: softmax over the 9 taps per (pixel, group) ----
    if (tid < TILE * GG) {
        const int pp = tid / GG, g = tid % GG;
        float* m = &msk[pp][g * PP];
        float mx = m[0];
        #pragma unroll
        for (int p = 1; p < PP; p++) mx = fmaxf(mx, m[p]);
        float e[PP], s = 0.f;
        #pragma unroll
        for (int p = 0; p < PP; p++) { e[p] = __expf(m[p] - mx); s += e[p]; }
        const float inv = 1.f / s;
        #pragma unroll
        for (int p = 0; p < PP; p++) m[p] = e[p] * inv;
    }
    __syncthreads();

    // ---- phase 2.5: per-(pixel,g,p) corner indices + mask-folded weights ----
    for (int idx = tid; idx < TILE * NMSK; idx += NTHR) {
        const int pp = idx / NMSK;
        const int gp = idx % NMSK;
        const int p  = gp % PP;
        const float dx = offs[pp][gp * 2 + 0];
        const float dy = offs[pp][gp * 2 + 1];
        // padded coords: px = w + p/3 + dx ; py = h + p%3 + dy
        const float px = (float)(w0 + pp) + (float)(p / 3) + dx;
        const float py = (float)h + (float)(p % 3) + dy;
        const float x0f = floorf(px), y0f = floorf(py);
        const float tx = px - x0f, ty = py - y0f;
        const int ix0 = (int)x0f, iy0 = (int)y0f;
        const float m = msk[pp][gp];

        const float wgt[4] = { (1.f - tx) * (1.f - ty) * m,
                               tx * (1.f - ty) * m,
                               (1.f - tx) * ty * m,
                               tx * ty * m };
        const int cx[4] = { ix0, ix0 + 1, ix0,     ix0 + 1 };
        const int cy[4] = { iy0, iy0,     iy0 + 1, iy0 + 1 };
        #pragma unroll
        for (int k = 0; k < 4; k++) {
            // nonzero contribution only if padded coord in [1,128] both axes
            const bool ok = ((unsigned)(cx[k] - 1) < (unsigned)WW) &&
                            ((unsigned)(cy[k] - 1) < (unsigned)HH);
            swt[pp][gp][k]  = ok ? wgt[k] : 0.f;
            sidx[pp][gp][k] = ok ? (((b * HH + (cy[k] - 1)) * WW + (cx[k] - 1)) * CC) : 0;
        }
    }
    __syncthreads();

    // ---- phase 3: gather + accumulate. warp = pixel, lane = float4 channel slot ----
    const int c4 = tid & 31;          // float4 slot -> channels [4*c4, 4*c4+3]
    const int g  = c4 >> 3;           // group of this channel slot
    const float4* in4 = reinterpret_cast<const float4*>(in);
    float4* out4 = reinterpret_cast<float4*>(out);

    #pragma unroll
    for (int pass = 0; pass < 2; pass++) {
        const int pp = (tid >> 5) + pass * 8;
        float4 acc = make_float4(0.f, 0.f, 0.f, 0.f);
        #pragma unroll
        for (int p = 0; p < PP; p++) {
            const int gp = g * PP + p;
            const int4   id = *reinterpret_cast<const int4*>(sidx[pp][gp]);
            const float4 wv = *reinterpret_cast<const float4*>(swt[pp][gp]);
            if (wv.x != 0.f) {
                const float4 v = in4[(id.x >> 2) + c4];
                acc.x = fmaf(wv.x, v.x, acc.x); acc.y = fmaf(wv.x, v.y, acc.y);
                acc.z = fmaf(wv.x, v.z, acc.z); acc.w = fmaf(wv.x, v.w, acc.w);
            }
            if (wv.y != 0.f) {
                const float4 v = in4[(id.y >> 2) + c4];
                acc.x = fmaf(wv.y, v.x, acc.x); acc.y = fmaf(wv.y, v.y, acc.y);
                acc.z = fmaf(wv.y, v.z, acc.z); acc.w = fmaf(wv.y, v.w, acc.w);
            }
            if (wv.z != 0.f) {
                const float4 v = in4[(id.z >> 2) + c4];
                acc.x = fmaf(wv.z, v.x, acc.x); acc.y = fmaf(wv.z, v.y, acc.y);
                acc.z = fmaf(wv.z, v.z, acc.z); acc.w = fmaf(wv.z, v.w, acc.w);
            }
            if (wv.w != 0.f) {
                const float4 v = in4[(id.w >> 2) + c4];
                acc.x = fmaf(wv.w, v.x, acc.x); acc.y = fmaf(wv.w, v.y, acc.y);
                acc.z = fmaf(wv.w, v.z, acc.z); acc.w = fmaf(wv.w, v.w, acc.w);
            }
        }
        const size_t o = (((size_t)b * HH + h) * WW + (w0 + pp)) * (CC / 4) + c4;
        out4[o] = acc;
    }
}

extern "C" void kernel_launch(void* const* d_in, const int* in_sizes, int n_in,
                              void* d_out, int out_size) {
    const float* inp   = (const float*)d_in[0];
    const float* Woff  = (const float*)d_in[1];
    const float* boff  = (const float*)d_in[2];
    const float* Wmask = (const float*)d_in[3];
    const float* bmask = (const float*)d_in[4];
    float* out = (float*)d_out;

    const int nblocks = BB * HH * (WW / TILE);   // 4*128*8 = 4096
    dcnv3_fused<<<nblocks, NTHR>>>(inp, Woff, boff, Wmask, bmask, out);
}